// round 9
// baseline (speedup 1.0000x reference)
#include <cuda_runtime.h>
#include <cuda_bf16.h>

// GlobalContextBlock (GCNet) — single-kernel, per-batch dataflow pipeline.
// Shapes fixed: B=32, H=W=64 (HW=4096), C=256, HEADS=8, c1=32, planes=64.
//
// 1024 blocks (32 per batch), 256 threads. Per block:
//   phase A: pool its 128-position chunk (one streaming read of the chunk),
//            write partials (exp w/o max-subtraction: |logit| < ~7).
//   last-arriving block of the batch (atomic counter): reduce -> ctx ->
//            MLP(256->64, LN eps=1e-3, ReLU, 64->256) -> g_term, raise flag[b].
//   others:  spin (tid0 + nanosleep) on flag[b] only — no grid barrier, so
//            batches pipeline freely.
//   phase B: re-walk OWN chunk in REVERSE (same addresses, same SM -> L1 hits;
//            L1 persists within a launch on sm_103a) doing out = x + term.
// All counters/flags self-reset -> graph-replay safe.

#define HW    4096
#define C     256
#define HEADS 8
#define PLANES 64
#define NCHUNK 32                      // blocks per batch
#define POS_PER_CHUNK (HW / NCHUNK)    // 128
#define MAXB  64
#define UB 8

__device__ float    g_pnum[MAXB * NCHUNK * C];
__device__ float    g_pden[MAXB * NCHUNK * HEADS];
__device__ float    g_term[MAXB * C];
__device__ unsigned g_bar[MAXB];       // pool-arrival counter (self-reset)
__device__ unsigned g_flag[MAXB];      // term-ready flag      (self-reset)
__device__ unsigned g_done[MAXB];      // add-done counter     (self-reset)

__global__ __launch_bounds__(256, 3) void gc_fused_kernel(
    const float* __restrict__ x, const float* __restrict__ wm,
    const float* __restrict__ bmp,
    const float* __restrict__ w1, const float* __restrict__ b1,
    const float* __restrict__ gamma, const float* __restrict__ beta,
    const float* __restrict__ w2, const float* __restrict__ b2,
    float* __restrict__ out)
{
    const int blk   = blockIdx.x;
    const int b     = blk / NCHUNK;
    const int chunk = blk % NCHUNK;
    const int s0    = chunk * POS_PER_CHUNK;

    const int tid  = threadIdx.x;
    const int w    = tid >> 5;
    const int l    = tid & 31;
    const int half = w & 1;
    const int wrow = w >> 1;            // 0..3

    const float4 wmv = *reinterpret_cast<const float4*>(wm + 4 * (l & 7));
    const float  bm  = bmp[0];

    const size_t off = ((size_t)b * HW + s0 + wrow) * C + half * 128 + 4 * l;
    const float* base = x + off;

    // ========================  Phase A: pooling  ===========================
    float4 acc = make_float4(0.f, 0.f, 0.f, 0.f);
    float  den = 0.f;

    #pragma unroll
    for (int kk = 0; kk < POS_PER_CHUNK / 4 / UB; kk++) {
        float4 xv[UB];
        #pragma unroll
        for (int u = 0; u < UB; u++)
            xv[u] = *reinterpret_cast<const float4*>(
                base + (size_t)(kk * UB + u) * 4 * C);

        float p[UB];
        #pragma unroll
        for (int u = 0; u < UB; u++)
            p[u] = xv[u].x * wmv.x + xv[u].y * wmv.y +
                   xv[u].z * wmv.z + xv[u].w * wmv.w;

        #pragma unroll
        for (int u = 0; u < UB; u++) p[u] += __shfl_xor_sync(0xFFFFFFFFu, p[u], 1);
        #pragma unroll
        for (int u = 0; u < UB; u++) p[u] += __shfl_xor_sync(0xFFFFFFFFu, p[u], 2);
        #pragma unroll
        for (int u = 0; u < UB; u++) p[u] += __shfl_xor_sync(0xFFFFFFFFu, p[u], 4);

        float e[UB];
        #pragma unroll
        for (int u = 0; u < UB; u++) e[u] = __expf(p[u] + bm);

        #pragma unroll
        for (int u = 0; u < UB; u++) {
            acc.x = fmaf(e[u], xv[u].x, acc.x);
            acc.y = fmaf(e[u], xv[u].y, acc.y);
            acc.z = fmaf(e[u], xv[u].z, acc.z);
            acc.w = fmaf(e[u], xv[u].w, acc.w);
            den  += e[u];
        }
    }

    __shared__ float s_num[8][128];
    __shared__ float s_den[8][4];
    s_num[w][4 * l + 0] = acc.x;
    s_num[w][4 * l + 1] = acc.y;
    s_num[w][4 * l + 2] = acc.z;
    s_num[w][4 * l + 3] = acc.w;
    if ((l & 7) == 0) s_den[w][l >> 3] = den;
    __syncthreads();

    {
        const int ch = tid;            // 0..255
        const int hf = ch >> 7;
        const int cl = ch & 127;
        g_pnum[(size_t)blk * C + ch] =
            s_num[hf][cl] + s_num[hf + 2][cl] + s_num[hf + 4][cl] + s_num[hf + 6][cl];
    }
    if (tid < HEADS) {
        const int hf = tid >> 2;
        const int hh = tid & 3;
        g_pden[(size_t)blk * HEADS + tid] =
            s_den[hf][hh] + s_den[hf + 2][hh] + s_den[hf + 4][hh] + s_den[hf + 6][hh];
    }

    // ------------- last-block-per-batch detection ------------------------
    __shared__ int s_last;
    __threadfence();                   // publish partials
    __syncthreads();
    if (tid == 0) {
        const unsigned old = atomicAdd(&g_bar[b], 1u);
        s_last = (old == NCHUNK - 1u);
        if (s_last) g_bar[b] = 0u;     // self-reset
    }
    __syncthreads();

    if (s_last) {
        // =====================  MLP for batch b  ===========================
        __shared__ float s_ctx[C];
        __shared__ float s_y[PLANES];
        __shared__ float s_stats[2];
        __threadfence();               // acquire all 32 blocks' partials

        {
            const int c = tid;
            const int head = c >> 5;
            float num = 0.f, dn = 0.f;
            #pragma unroll
            for (int ch = 0; ch < NCHUNK; ch++) {
                num += g_pnum[((size_t)b * NCHUNK + ch) * C + c];
                dn  += g_pden[((size_t)b * NCHUNK + ch) * HEADS + head];
            }
            s_ctx[c] = num / dn;
        }
        __syncthreads();

        {
            const int p = tid >> 2;
            const int q = tid & 3;
            float a2 = 0.f;
            #pragma unroll 8
            for (int i = 0; i < 64; i++) {
                const int c = q * 64 + i;
                a2 = fmaf(s_ctx[c], w1[c * PLANES + p], a2);
            }
            a2 += __shfl_xor_sync(0xFFFFFFFFu, a2, 1);
            a2 += __shfl_xor_sync(0xFFFFFFFFu, a2, 2);
            if (q == 0) s_y[p] = a2 + b1[p];
        }
        __syncthreads();

        if (tid < 32) {
            const float v1 = s_y[tid];
            const float v2 = s_y[tid + 32];
            float s  = v1 + v2;
            float sq = v1 * v1 + v2 * v2;
            #pragma unroll
            for (int m = 16; m > 0; m >>= 1) {
                s  += __shfl_xor_sync(0xFFFFFFFFu, s,  m);
                sq += __shfl_xor_sync(0xFFFFFFFFu, sq, m);
            }
            if (tid == 0) {
                const float mean = s / 64.f;
                const float var  = sq / 64.f - mean * mean;
                s_stats[0] = mean;
                s_stats[1] = rsqrtf(var + 1e-3f);
            }
        }
        __syncthreads();

        if (tid < PLANES) {
            const float v = (s_y[tid] - s_stats[0]) * s_stats[1] * gamma[tid] + beta[tid];
            s_y[tid] = fmaxf(v, 0.f);
        }
        __syncthreads();

        {
            const int c = tid;
            float a3 = b2[c];
            #pragma unroll 8
            for (int p = 0; p < PLANES; p++)
                a3 = fmaf(s_y[p], w2[p * C + c], a3);
            g_term[(size_t)b * C + c] = a3;
        }
        __syncthreads();
        __threadfence();               // publish g_term
        if (tid == 0) atomicExch(&g_flag[b], 1u);
    } else {
        // wait for this batch's term (per-batch, not grid-wide)
        if (tid == 0) {
            while (atomicAdd(&g_flag[b], 0u) == 0u) __nanosleep(128);
        }
        __syncthreads();
        __threadfence();               // acquire g_term
    }

    // ============  Phase B: out = x + term, reverse re-walk  ===============
    {
        const float4 tv = *reinterpret_cast<const float4*>(
            g_term + b * C + half * 128 + 4 * l);
        float* ob = out + off;

        #pragma unroll
        for (int kk = POS_PER_CHUNK / 4 / UB - 1; kk >= 0; kk--) {
            float4 v[UB];
            #pragma unroll
            for (int u = 0; u < UB; u++)
                v[u] = *reinterpret_cast<const float4*>(
                    base + (size_t)(kk * UB + u) * 4 * C);
            #pragma unroll
            for (int u = 0; u < UB; u++) {
                v[u].x += tv.x; v[u].y += tv.y; v[u].z += tv.z; v[u].w += tv.w;
                __stcs(reinterpret_cast<float4*>(ob + (size_t)(kk * UB + u) * 4 * C),
                       v[u]);
            }
        }
    }

    // ------------- self-reset of flag after all 32 blocks pass -------------
    __syncthreads();
    if (tid == 0) {
        const unsigned old = atomicAdd(&g_done[b], 1u);
        if (old == NCHUNK - 1u) {
            g_done[b] = 0u;
            g_flag[b] = 0u;
            __threadfence();
        }
    }
}

extern "C" void kernel_launch(void* const* d_in, const int* in_sizes, int n_in,
                              void* d_out, int out_size)
{
    const float* x     = (const float*)d_in[0];
    const float* wm    = (const float*)d_in[1];
    const float* bm    = (const float*)d_in[2];
    const float* w1    = (const float*)d_in[3];
    const float* b1    = (const float*)d_in[4];
    const float* gamma = (const float*)d_in[5];
    const float* beta  = (const float*)d_in[6];
    const float* w2    = (const float*)d_in[7];
    const float* b2    = (const float*)d_in[8];
    float* out = (float*)d_out;

    const int B = in_sizes[0] / (HW * C);

    gc_fused_kernel<<<B * NCHUNK, 256>>>(x, wm, bm, w1, b1, gamma, beta,
                                         w2, b2, out);
}

// round 10
// speedup vs baseline: 2.2819x; 2.2819x over previous
#include <cuda_runtime.h>
#include <cuda_bf16.h>

// GlobalContextBlock (GCNet) — single persistent work-stealing kernel.
// Shapes fixed: B=32, H=W=64 (HW=4096), C=256, HEADS=8, c1=32, planes=64.
//
// 444 resident blocks (148 SMs x 3 CTAs), 256 threads. Two ticket queues:
//   pool tickets (1024): stream-read a 128-position chunk, softmax-pooling
//     partials (exp w/o max-subtraction: |logit| < ~7, fp32-safe). The
//     last-finishing block of each batch runs the bottleneck MLP inline
//     (256->64, LN eps=1e-3, ReLU, 64->256) and raises flag[b].
//     NO block ever waits in this phase.
//   add tickets (4096, ascending): out = x + term[b]. May briefly wait on
//     flag[b], but all pool work is drained by resident blocks first, so
//     waits are bounded -> deadlock-free at any residency (the round-9
//     failure mode: resident blocks waiting on non-resident producers).
// Counters/flags reset by the last-exiting block -> graph-replay safe.

#define HW    4096
#define C     256
#define C4    64
#define HEADS 8
#define PLANES 64
#define NCHUNK 32                       // pool chunks per batch
#define POS_PER_CHUNK (HW / NCHUNK)     // 128
#define NPOOL_T (32 * NCHUNK)           // 1024 pool tickets (B=32)
#define ADD_ELE 2048                    // float4 per add ticket
#define NADD_T  4096                    // add tickets (8,388,608 / 2048)
#define ADD_PER_BATCH (NADD_T / 32)     // 128
#define MAXB  64
#define UB 8
#define NBLOCKS 444

__device__ float    g_pnum[MAXB * NCHUNK * C];
__device__ float    g_pden[MAXB * NCHUNK * HEADS];
__device__ float    g_term[MAXB * C];
__device__ unsigned g_bar[MAXB];        // pool-arrival counter per batch
__device__ unsigned g_flag[MAXB];       // term-ready flag per batch
__device__ unsigned g_pool_ticket;
__device__ unsigned g_add_ticket;
__device__ unsigned g_done;

__global__ __launch_bounds__(256, 3) void gc_ws_kernel(
    const float* __restrict__ x, const float* __restrict__ wm,
    const float* __restrict__ bmp,
    const float* __restrict__ w1, const float* __restrict__ b1,
    const float* __restrict__ gamma, const float* __restrict__ beta,
    const float* __restrict__ w2, const float* __restrict__ b2,
    float* __restrict__ out)
{
    const int tid  = threadIdx.x;
    const int w    = tid >> 5;
    const int l    = tid & 31;
    const int half = w & 1;
    const int wrow = w >> 1;            // 0..3

    const float4 wmv = *reinterpret_cast<const float4*>(wm + 4 * (l & 7));
    const float  bm  = bmp[0];

    __shared__ int   s_ticket;
    __shared__ int   s_last;
    __shared__ float s_num[8][128];
    __shared__ float s_den[8][4];
    __shared__ float s_ctx[C];
    __shared__ float s_y[PLANES];
    __shared__ float s_stats[2];

    // ====================== Phase 1: pool tickets ==========================
    for (;;) {
        if (tid == 0) s_ticket = (int)atomicAdd(&g_pool_ticket, 1u);
        __syncthreads();
        const int t = s_ticket;
        __syncthreads();
        if (t >= NPOOL_T) break;

        const int b     = t / NCHUNK;
        const int chunk = t % NCHUNK;
        const int s0    = chunk * POS_PER_CHUNK;
        const float* base =
            x + ((size_t)b * HW + s0 + wrow) * C + half * 128 + 4 * l;

        float4 acc = make_float4(0.f, 0.f, 0.f, 0.f);
        float  den = 0.f;

        #pragma unroll
        for (int kk = 0; kk < POS_PER_CHUNK / 4 / UB; kk++) {
            float4 xv[UB];
            #pragma unroll
            for (int u = 0; u < UB; u++)
                xv[u] = *reinterpret_cast<const float4*>(
                    base + (size_t)(kk * UB + u) * 4 * C);

            float p[UB];
            #pragma unroll
            for (int u = 0; u < UB; u++)
                p[u] = xv[u].x * wmv.x + xv[u].y * wmv.y +
                       xv[u].z * wmv.z + xv[u].w * wmv.w;

            #pragma unroll
            for (int u = 0; u < UB; u++) p[u] += __shfl_xor_sync(0xFFFFFFFFu, p[u], 1);
            #pragma unroll
            for (int u = 0; u < UB; u++) p[u] += __shfl_xor_sync(0xFFFFFFFFu, p[u], 2);
            #pragma unroll
            for (int u = 0; u < UB; u++) p[u] += __shfl_xor_sync(0xFFFFFFFFu, p[u], 4);

            float e[UB];
            #pragma unroll
            for (int u = 0; u < UB; u++) e[u] = __expf(p[u] + bm);

            #pragma unroll
            for (int u = 0; u < UB; u++) {
                acc.x = fmaf(e[u], xv[u].x, acc.x);
                acc.y = fmaf(e[u], xv[u].y, acc.y);
                acc.z = fmaf(e[u], xv[u].z, acc.z);
                acc.w = fmaf(e[u], xv[u].w, acc.w);
                den  += e[u];
            }
        }

        s_num[w][4 * l + 0] = acc.x;
        s_num[w][4 * l + 1] = acc.y;
        s_num[w][4 * l + 2] = acc.z;
        s_num[w][4 * l + 3] = acc.w;
        if ((l & 7) == 0) s_den[w][l >> 3] = den;
        __syncthreads();

        {
            const int ch = tid;
            const int hf = ch >> 7;
            const int cl = ch & 127;
            g_pnum[(size_t)t * C + ch] = s_num[hf][cl] + s_num[hf + 2][cl] +
                                         s_num[hf + 4][cl] + s_num[hf + 6][cl];
        }
        if (tid < HEADS) {
            const int hf = tid >> 2;
            const int hh = tid & 3;
            g_pden[(size_t)t * HEADS + tid] =
                s_den[hf][hh] + s_den[hf + 2][hh] +
                s_den[hf + 4][hh] + s_den[hf + 6][hh];
        }

        __threadfence();               // publish partials
        __syncthreads();
        if (tid == 0) {
            const unsigned old = atomicAdd(&g_bar[b], 1u);
            s_last = (old == NCHUNK - 1u);
            if (s_last) g_bar[b] = 0u; // self-reset
        }
        __syncthreads();

        if (s_last) {
            // ---------------- inline MLP for batch b ----------------------
            __threadfence();           // acquire all partials
            {
                const int c = tid;
                const int head = c >> 5;
                float num = 0.f, dn = 0.f;
                #pragma unroll
                for (int ch = 0; ch < NCHUNK; ch++) {
                    num += g_pnum[((size_t)b * NCHUNK + ch) * C + c];
                    dn  += g_pden[((size_t)b * NCHUNK + ch) * HEADS + head];
                }
                s_ctx[c] = num / dn;
            }
            __syncthreads();

            {
                const int p = tid >> 2;
                const int q = tid & 3;
                float a2 = 0.f;
                #pragma unroll 8
                for (int i = 0; i < 64; i++) {
                    const int c = q * 64 + i;
                    a2 = fmaf(s_ctx[c], w1[c * PLANES + p], a2);
                }
                a2 += __shfl_xor_sync(0xFFFFFFFFu, a2, 1);
                a2 += __shfl_xor_sync(0xFFFFFFFFu, a2, 2);
                if (q == 0) s_y[p] = a2 + b1[p];
            }
            __syncthreads();

            if (tid < 32) {
                const float v1 = s_y[tid];
                const float v2 = s_y[tid + 32];
                float s  = v1 + v2;
                float sq = v1 * v1 + v2 * v2;
                #pragma unroll
                for (int m = 16; m > 0; m >>= 1) {
                    s  += __shfl_xor_sync(0xFFFFFFFFu, s,  m);
                    sq += __shfl_xor_sync(0xFFFFFFFFu, sq, m);
                }
                if (tid == 0) {
                    const float mean = s / 64.f;
                    const float var  = sq / 64.f - mean * mean;
                    s_stats[0] = mean;
                    s_stats[1] = rsqrtf(var + 1e-3f);
                }
            }
            __syncthreads();

            if (tid < PLANES) {
                const float v = (s_y[tid] - s_stats[0]) * s_stats[1] * gamma[tid]
                                + beta[tid];
                s_y[tid] = fmaxf(v, 0.f);
            }
            __syncthreads();

            {
                const int c = tid;
                float a3 = b2[c];
                #pragma unroll 8
                for (int p = 0; p < PLANES; p++)
                    a3 = fmaf(s_y[p], w2[p * C + c], a3);
                g_term[(size_t)b * C + c] = a3;
            }
            __syncthreads();
            __threadfence();           // publish g_term
            if (tid == 0) atomicExch(&g_flag[b], 1u);
            __syncthreads();
        }
    }

    // ====================== Phase 2: add tickets ===========================
    const float4* x4   = reinterpret_cast<const float4*>(x);
    float4*       out4 = reinterpret_cast<float4*>(out);

    for (;;) {
        if (tid == 0) s_ticket = (int)atomicAdd(&g_add_ticket, 1u);
        __syncthreads();
        const int t = s_ticket;
        __syncthreads();
        if (t >= NADD_T) break;

        const int b = t / ADD_PER_BATCH;
        if (tid == 0) {
            while (atomicAdd(&g_flag[b], 0u) == 0u) __nanosleep(64);
        }
        __syncthreads();
        __threadfence();               // acquire g_term[b]

        const size_t base = (size_t)t * ADD_ELE + tid;
        float4 v[UB];
        #pragma unroll
        for (int k = 0; k < UB; k++)
            v[k] = __ldcs(x4 + base + (size_t)k * 256);

        #pragma unroll
        for (int k = 0; k < UB; k++) {
            const size_t i = base + (size_t)k * 256;
            const int c4 = (int)(i & (C4 - 1));
            const float4 tv = reinterpret_cast<const float4*>(g_term)[b * C4 + c4];
            v[k].x += tv.x; v[k].y += tv.y; v[k].z += tv.z; v[k].w += tv.w;
            __stcs(out4 + i, v[k]);
        }
    }

    // ================== last-block reset (replay-safe) =====================
    __syncthreads();
    if (tid == 0) {
        const unsigned old = atomicAdd(&g_done, 1u);
        if (old == NBLOCKS - 1u) {
            g_pool_ticket = 0u;
            g_add_ticket  = 0u;
            g_done        = 0u;
            #pragma unroll
            for (int b = 0; b < 32; b++) g_flag[b] = 0u;
            __threadfence();
        }
    }
}

extern "C" void kernel_launch(void* const* d_in, const int* in_sizes, int n_in,
                              void* d_out, int out_size)
{
    const float* x     = (const float*)d_in[0];
    const float* wm    = (const float*)d_in[1];
    const float* bm    = (const float*)d_in[2];
    const float* w1    = (const float*)d_in[3];
    const float* b1    = (const float*)d_in[4];
    const float* gamma = (const float*)d_in[5];
    const float* beta  = (const float*)d_in[6];
    const float* w2    = (const float*)d_in[7];
    const float* b2    = (const float*)d_in[8];
    float* out = (float*)d_out;

    gc_ws_kernel<<<NBLOCKS, 256>>>(x, wm, bm, w1, b1, gamma, beta, w2, b2, out);
}

// round 13
// speedup vs baseline: 2.3951x; 1.0496x over previous
#include <cuda_runtime.h>
#include <cuda_bf16.h>

// GlobalContextBlock (GCNet) — single persistent work-stealing kernel, v2.
// Shapes fixed: B=32, H=W=64 (HW=4096), C=256, HEADS=8, c1=32, planes=64.
//
// Round-10 lesson: the dataflow was right, occupancy was wrong (3 CTAs/SM =
// 24 warps starved the add phase; R8's add needed ~40 warps to hit 5.65TB/s).
// v2: pool ILP 8->4 so regs fit 64 -> __launch_bounds__(256,4) -> 32 warps/SM,
// 592 blocks (148 SMs x 4).
//
// Two ticket queues (atomic counters):
//   pool tickets (1024): stream-read a 128-position chunk, softmax-pooling
//     partials (exp w/o max-subtraction: |logit| < ~7). Last-finishing block
//     of each batch runs the MLP inline (256->64, LN eps=1e-3, ReLU, 64->256)
//     and raises flag[b]. No waiting in this phase.
//   add tickets (4096, ascending): out = x + term[b]; brief wait on flag[b]
//     only (pool drains first; ascending order -> flags ~always ready).
// Counters/flags reset by last-exiting block -> graph-replay safe.

#define HW    4096
#define C     256
#define C4    64
#define HEADS 8
#define PLANES 64
#define NCHUNK 32                       // pool chunks per batch
#define POS_PER_CHUNK (HW / NCHUNK)     // 128
#define NPOOL_T (32 * NCHUNK)           // 1024 pool tickets (B=32)
#define ADD_ELE 2048                    // float4 per add ticket (32KB)
#define NADD_T  4096                    // 8,388,608 / 2048
#define ADD_PER_BATCH (NADD_T / 32)     // 128
#define MAXB  64
#define UBP 4                           // pool position batch (fits 64 regs)
#define UBA 8                           // add float4 batch
#define NBLOCKS 592

__device__ float    g_pnum[MAXB * NCHUNK * C];
__device__ float    g_pden[MAXB * NCHUNK * HEADS];
__device__ float    g_term[MAXB * C];
__device__ unsigned g_bar[MAXB];        // pool-arrival counter per batch
__device__ unsigned g_flag[MAXB];       // term-ready flag per batch
__device__ unsigned g_pool_ticket;
__device__ unsigned g_add_ticket;
__device__ unsigned g_done;

__global__ __launch_bounds__(256, 4) void gc_ws2_kernel(
    const float* __restrict__ x, const float* __restrict__ wm,
    const float* __restrict__ bmp,
    const float* __restrict__ w1, const float* __restrict__ b1,
    const float* __restrict__ gamma, const float* __restrict__ beta,
    const float* __restrict__ w2, const float* __restrict__ b2,
    float* __restrict__ out)
{
    const int tid  = threadIdx.x;
    const int w    = tid >> 5;
    const int l    = tid & 31;
    const int half = w & 1;
    const int wrow = w >> 1;            // 0..3

    const float4 wmv = *reinterpret_cast<const float4*>(wm + 4 * (l & 7));
    const float  bm  = bmp[0];

    __shared__ int   s_ticket;
    __shared__ int   s_last;
    __shared__ float s_num[8][128];
    __shared__ float s_den[8][4];
    __shared__ float s_ctx[C];
    __shared__ float s_y[PLANES];
    __shared__ float s_stats[2];

    // ====================== Phase 1: pool tickets ==========================
    for (;;) {
        if (tid == 0) s_ticket = (int)atomicAdd(&g_pool_ticket, 1u);
        __syncthreads();
        const int t = s_ticket;
        __syncthreads();
        if (t >= NPOOL_T) break;

        const int b     = t / NCHUNK;
        const int chunk = t % NCHUNK;
        const int s0    = chunk * POS_PER_CHUNK;
        const float* base =
            x + ((size_t)b * HW + s0 + wrow) * C + half * 128 + 4 * l;

        float4 acc = make_float4(0.f, 0.f, 0.f, 0.f);
        float  den = 0.f;

        // 32 positions per warp, batches of UBP=4.
        #pragma unroll
        for (int kk = 0; kk < POS_PER_CHUNK / 4 / UBP; kk++) {
            float4 xv[UBP];
            #pragma unroll
            for (int u = 0; u < UBP; u++)
                xv[u] = *reinterpret_cast<const float4*>(
                    base + (size_t)(kk * UBP + u) * 4 * C);

            float p[UBP];
            #pragma unroll
            for (int u = 0; u < UBP; u++)
                p[u] = xv[u].x * wmv.x + xv[u].y * wmv.y +
                       xv[u].z * wmv.z + xv[u].w * wmv.w;

            #pragma unroll
            for (int u = 0; u < UBP; u++) p[u] += __shfl_xor_sync(0xFFFFFFFFu, p[u], 1);
            #pragma unroll
            for (int u = 0; u < UBP; u++) p[u] += __shfl_xor_sync(0xFFFFFFFFu, p[u], 2);
            #pragma unroll
            for (int u = 0; u < UBP; u++) p[u] += __shfl_xor_sync(0xFFFFFFFFu, p[u], 4);

            float e[UBP];
            #pragma unroll
            for (int u = 0; u < UBP; u++) e[u] = __expf(p[u] + bm);

            #pragma unroll
            for (int u = 0; u < UBP; u++) {
                acc.x = fmaf(e[u], xv[u].x, acc.x);
                acc.y = fmaf(e[u], xv[u].y, acc.y);
                acc.z = fmaf(e[u], xv[u].z, acc.z);
                acc.w = fmaf(e[u], xv[u].w, acc.w);
                den  += e[u];
            }
        }

        s_num[w][4 * l + 0] = acc.x;
        s_num[w][4 * l + 1] = acc.y;
        s_num[w][4 * l + 2] = acc.z;
        s_num[w][4 * l + 3] = acc.w;
        if ((l & 7) == 0) s_den[w][l >> 3] = den;
        __syncthreads();

        {
            const int ch = tid;
            const int hf = ch >> 7;
            const int cl = ch & 127;
            g_pnum[(size_t)t * C + ch] = s_num[hf][cl] + s_num[hf + 2][cl] +
                                         s_num[hf + 4][cl] + s_num[hf + 6][cl];
        }
        if (tid < HEADS) {
            const int hf = tid >> 2;
            const int hh = tid & 3;
            g_pden[(size_t)t * HEADS + tid] =
                s_den[hf][hh] + s_den[hf + 2][hh] +
                s_den[hf + 4][hh] + s_den[hf + 6][hh];
        }

        __threadfence();               // publish partials
        __syncthreads();
        if (tid == 0) {
            const unsigned old = atomicAdd(&g_bar[b], 1u);
            s_last = (old == NCHUNK - 1u);
            if (s_last) g_bar[b] = 0u; // self-reset
        }
        __syncthreads();

        if (s_last) {
            // ---------------- inline MLP for batch b ----------------------
            __threadfence();           // acquire all partials
            {
                const int c = tid;
                const int head = c >> 5;
                float num = 0.f, dn = 0.f;
                #pragma unroll
                for (int ch = 0; ch < NCHUNK; ch++) {
                    num += g_pnum[((size_t)b * NCHUNK + ch) * C + c];
                    dn  += g_pden[((size_t)b * NCHUNK + ch) * HEADS + head];
                }
                s_ctx[c] = num / dn;
            }
            __syncthreads();

            {
                const int p = tid >> 2;
                const int q = tid & 3;
                float a2 = 0.f;
                #pragma unroll 8
                for (int i = 0; i < 64; i++) {
                    const int c = q * 64 + i;
                    a2 = fmaf(s_ctx[c], w1[c * PLANES + p], a2);
                }
                a2 += __shfl_xor_sync(0xFFFFFFFFu, a2, 1);
                a2 += __shfl_xor_sync(0xFFFFFFFFu, a2, 2);
                if (q == 0) s_y[p] = a2 + b1[p];
            }
            __syncthreads();

            if (tid < 32) {
                const float v1 = s_y[tid];
                const float v2 = s_y[tid + 32];
                float s  = v1 + v2;
                float sq = v1 * v1 + v2 * v2;
                #pragma unroll
                for (int m = 16; m > 0; m >>= 1) {
                    s  += __shfl_xor_sync(0xFFFFFFFFu, s,  m);
                    sq += __shfl_xor_sync(0xFFFFFFFFu, sq, m);
                }
                if (tid == 0) {
                    const float mean = s / 64.f;
                    const float var  = sq / 64.f - mean * mean;
                    s_stats[0] = mean;
                    s_stats[1] = rsqrtf(var + 1e-3f);
                }
            }
            __syncthreads();

            if (tid < PLANES) {
                const float v = (s_y[tid] - s_stats[0]) * s_stats[1] * gamma[tid]
                                + beta[tid];
                s_y[tid] = fmaxf(v, 0.f);
            }
            __syncthreads();

            {
                const int c = tid;
                float a3 = b2[c];
                #pragma unroll 8
                for (int p = 0; p < PLANES; p++)
                    a3 = fmaf(s_y[p], w2[p * C + c], a3);
                g_term[(size_t)b * C + c] = a3;
            }
            __syncthreads();
            __threadfence();           // publish g_term
            if (tid == 0) atomicExch(&g_flag[b], 1u);
            __syncthreads();
        }
    }

    // ====================== Phase 2: add tickets ===========================
    const float4* x4   = reinterpret_cast<const float4*>(x);
    float4*       out4 = reinterpret_cast<float4*>(out);
    int ready_b = -1;                  // highest batch already acquired

    for (;;) {
        if (tid == 0) s_ticket = (int)atomicAdd(&g_add_ticket, 1u);
        __syncthreads();
        const int t = s_ticket;
        __syncthreads();
        if (t >= NADD_T) break;

        const int b = t / ADD_PER_BATCH;
        if (b > ready_b) {             // acquire once per new batch
            if (tid == 0) {
                while (atomicAdd(&g_flag[b], 0u) == 0u) __nanosleep(64);
            }
            __syncthreads();
            __threadfence();           // acquire g_term[b]
            ready_b = b;
        }

        const size_t base = (size_t)t * ADD_ELE + tid;
        float4 v[UBA];
        #pragma unroll
        for (int k = 0; k < UBA; k++)
            v[k] = __ldcs(x4 + base + (size_t)k * 256);

        #pragma unroll
        for (int k = 0; k < UBA; k++) {
            const size_t i = base + (size_t)k * 256;
            const int c4 = (int)(i & (C4 - 1));
            const float4 tv = reinterpret_cast<const float4*>(g_term)[b * C4 + c4];
            v[k].x += tv.x; v[k].y += tv.y; v[k].z += tv.z; v[k].w += tv.w;
            __stcs(out4 + i, v[k]);
        }
    }

    // ================== last-block reset (replay-safe) =====================
    __syncthreads();
    if (tid == 0) {
        const unsigned old = atomicAdd(&g_done, 1u);
        if (old == NBLOCKS - 1u) {
            g_pool_ticket = 0u;
            g_add_ticket  = 0u;
            g_done        = 0u;
            #pragma unroll
            for (int b = 0; b < 32; b++) g_flag[b] = 0u;
            __threadfence();
        }
    }
}

extern "C" void kernel_launch(void* const* d_in, const int* in_sizes, int n_in,
                              void* d_out, int out_size)
{
    const float* x     = (const float*)d_in[0];
    const float* wm    = (const float*)d_in[1];
    const float* bm    = (const float*)d_in[2];
    const float* w1    = (const float*)d_in[3];
    const float* b1    = (const float*)d_in[4];
    const float* gamma = (const float*)d_in[5];
    const float* beta  = (const float*)d_in[6];
    const float* w2    = (const float*)d_in[7];
    const float* b2    = (const float*)d_in[8];
    float* out = (float*)d_out;

    gc_ws2_kernel<<<NBLOCKS, 256>>>(x, wm, bm, w1, b1, gamma, beta, w2, b2, out);
}

// round 15
// speedup vs baseline: 2.5787x; 1.0767x over previous
#include <cuda_runtime.h>
#include <cuda_bf16.h>

// GlobalContextBlock (GCNet) — 2-kernel implementation + PDL overlap.
// Shapes fixed: B=32, H=W=64 (HW=4096), C=256, HEADS=8, c1=32, planes=64.
//
// k1: one streaming pass over x computing softmax-pooling partials
//     (exp w/o max-subtraction: |logit| < ~7, fp32-safe), with the bottleneck
//     MLP fused via the last-block-per-batch pattern: the last pool block of
//     each batch reduces partials -> ctx -> MLP(256->64, LN eps=1e-3, ReLU,
//     64->256) -> g_term.
// k2: out = x + term[b][c], launched with programmatic stream serialization
//     (PDL). Its blocks start while k1 drains, front-issue the read-only x
//     loads, then cudaGridDependencySynchronize() (k1 never triggers early ->
//     sync = full k1 completion) before reading g_term and storing. This
//     hides the launch gap + k1 straggler tail + MLP epilogue (~10us serial
//     overhead measured in round 8).

#define HW    4096
#define C     256
#define C4    64
#define HEADS 8
#define PLANES 64
#define NCHUNK 32                      // spatial chunks per batch in k1
#define POS_PER_CHUNK (HW / NCHUNK)    // 128
#define MAXB  64

__device__ float    g_pnum[MAXB * NCHUNK * C];
__device__ float    g_pden[MAXB * NCHUNK * HEADS];
__device__ float    g_term[MAXB * C];
__device__ unsigned g_bar[MAXB];       // per-batch arrival counters (self-reset)

// ---------------------------------------------------------------------------
// Kernel 1: pooling partials + fused last-block MLP.
// grid = B*NCHUNK, 256 threads (8 warps). Warp w: half=w&1 -> 128 channels;
// positions s0 + (w>>1) + 4k. Lane l owns channels half*128+4l..4l+3.
// UB=8 positions batched; __launch_bounds__(256,3) keeps loads in flight.
// ---------------------------------------------------------------------------
#define UB 8
__global__ __launch_bounds__(256, 3) void gc_pool_mlp_kernel(
    const float* __restrict__ x, const float* __restrict__ wm,
    const float* __restrict__ bmp,
    const float* __restrict__ w1, const float* __restrict__ b1,
    const float* __restrict__ gamma, const float* __restrict__ beta,
    const float* __restrict__ w2, const float* __restrict__ b2)
{
    const int blk   = blockIdx.x;
    const int b     = blk / NCHUNK;
    const int chunk = blk % NCHUNK;
    const int s0    = chunk * POS_PER_CHUNK;

    const int tid  = threadIdx.x;
    const int w    = tid >> 5;
    const int l    = tid & 31;
    const int half = w & 1;
    const int wrow = w >> 1;            // 0..3

    const float4 wmv = *reinterpret_cast<const float4*>(wm + 4 * (l & 7));
    const float  bm  = bmp[0];

    const float* base = x + ((size_t)b * HW + s0 + wrow) * C + half * 128 + 4 * l;

    float4 acc = make_float4(0.f, 0.f, 0.f, 0.f);
    float  den = 0.f;

    #pragma unroll
    for (int kk = 0; kk < POS_PER_CHUNK / 4 / UB; kk++) {
        float4 xv[UB];
        #pragma unroll
        for (int u = 0; u < UB; u++)
            xv[u] = *reinterpret_cast<const float4*>(
                base + (size_t)(kk * UB + u) * 4 * C);

        float p[UB];
        #pragma unroll
        for (int u = 0; u < UB; u++)
            p[u] = xv[u].x * wmv.x + xv[u].y * wmv.y +
                   xv[u].z * wmv.z + xv[u].w * wmv.w;

        #pragma unroll
        for (int u = 0; u < UB; u++) p[u] += __shfl_xor_sync(0xFFFFFFFFu, p[u], 1);
        #pragma unroll
        for (int u = 0; u < UB; u++) p[u] += __shfl_xor_sync(0xFFFFFFFFu, p[u], 2);
        #pragma unroll
        for (int u = 0; u < UB; u++) p[u] += __shfl_xor_sync(0xFFFFFFFFu, p[u], 4);

        float e[UB];
        #pragma unroll
        for (int u = 0; u < UB; u++) e[u] = __expf(p[u] + bm);

        #pragma unroll
        for (int u = 0; u < UB; u++) {
            acc.x = fmaf(e[u], xv[u].x, acc.x);
            acc.y = fmaf(e[u], xv[u].y, acc.y);
            acc.z = fmaf(e[u], xv[u].z, acc.z);
            acc.w = fmaf(e[u], xv[u].w, acc.w);
            den  += e[u];
        }
    }

    __shared__ float s_num[8][128];
    __shared__ float s_den[8][4];
    s_num[w][4 * l + 0] = acc.x;
    s_num[w][4 * l + 1] = acc.y;
    s_num[w][4 * l + 2] = acc.z;
    s_num[w][4 * l + 3] = acc.w;
    if ((l & 7) == 0) s_den[w][l >> 3] = den;
    __syncthreads();

    {
        const int ch = tid;            // 0..255
        const int hf = ch >> 7;
        const int cl = ch & 127;
        g_pnum[(size_t)blk * C + ch] =
            s_num[hf][cl] + s_num[hf + 2][cl] + s_num[hf + 4][cl] + s_num[hf + 6][cl];
    }
    if (tid < HEADS) {
        const int hf = tid >> 2;
        const int hh = tid & 3;
        g_pden[(size_t)blk * HEADS + tid] =
            s_den[hf][hh] + s_den[hf + 2][hh] + s_den[hf + 4][hh] + s_den[hf + 6][hh];
    }

    // ---- last-block-per-batch detection (threadFenceReduction pattern) ----
    __shared__ int s_last;
    __threadfence();                   // publish this block's partials
    __syncthreads();
    if (tid == 0) {
        const unsigned old = atomicAdd(&g_bar[b], 1u);
        s_last = (old == NCHUNK - 1u);
        if (s_last) g_bar[b] = 0u;     // self-reset for next graph replay
    }
    __syncthreads();
    if (!s_last) return;
    __threadfence();                   // acquire: see all 32 blocks' partials

    // =====================  fused MLP for batch b  ==========================
    __shared__ float s_ctx[C];
    __shared__ float s_y[PLANES];
    __shared__ float s_stats[2];

    {
        const int c = tid;
        const int head = c >> 5;
        float num = 0.f, dn = 0.f;
        #pragma unroll
        for (int ch = 0; ch < NCHUNK; ch++) {
            num += g_pnum[((size_t)b * NCHUNK + ch) * C + c];
            dn  += g_pden[((size_t)b * NCHUNK + ch) * HEADS + head];
        }
        s_ctx[c] = num / dn;
    }
    __syncthreads();

    {
        const int p = tid >> 2;
        const int q = tid & 3;
        float a2 = 0.f;
        #pragma unroll 8
        for (int i = 0; i < 64; i++) {
            const int c = q * 64 + i;
            a2 = fmaf(s_ctx[c], w1[c * PLANES + p], a2);
        }
        a2 += __shfl_xor_sync(0xFFFFFFFFu, a2, 1);
        a2 += __shfl_xor_sync(0xFFFFFFFFu, a2, 2);
        if (q == 0) s_y[p] = a2 + b1[p];
    }
    __syncthreads();

    if (tid < 32) {
        const float v1 = s_y[tid];
        const float v2 = s_y[tid + 32];
        float s  = v1 + v2;
        float sq = v1 * v1 + v2 * v2;
        #pragma unroll
        for (int m = 16; m > 0; m >>= 1) {
            s  += __shfl_xor_sync(0xFFFFFFFFu, s,  m);
            sq += __shfl_xor_sync(0xFFFFFFFFu, sq, m);
        }
        if (tid == 0) {
            const float mean = s / 64.f;
            const float var  = sq / 64.f - mean * mean;
            s_stats[0] = mean;
            s_stats[1] = rsqrtf(var + 1e-3f);
        }
    }
    __syncthreads();

    if (tid < PLANES) {
        const float v = (s_y[tid] - s_stats[0]) * s_stats[1] * gamma[tid] + beta[tid];
        s_y[tid] = fmaxf(v, 0.f);
    }
    __syncthreads();

    {
        const int c = tid;
        float a3 = b2[c];
        #pragma unroll 8
        for (int p = 0; p < PLANES; p++)
            a3 = fmaf(s_y[p], w2[p * C + c], a3);
        g_term[(size_t)b * C + c] = a3;
    }
}

// ---------------------------------------------------------------------------
// Kernel 2 (PDL secondary): out = x + term[b][c].
// Blocks may launch while k1 is still draining. The x loads are issued
// BEFORE cudaGridDependencySynchronize() (x is read-only input — always
// valid), so the first wave's memory fetches overlap k1's tail + MLP.
// g_term is only read after the sync. 8 float4/thread, no predicates
// (n4 = 8,388,608 is an exact multiple of 2048). 128-reg budget.
// ---------------------------------------------------------------------------
#define ADD_VPT 8
#define ADD_TPB 256
__global__ __launch_bounds__(ADD_TPB, 2) void gc_add_kernel(
    const float4* __restrict__ x4, float4* __restrict__ out4)
{
    const size_t base = (size_t)blockIdx.x * (ADD_TPB * ADD_VPT) + threadIdx.x;

    float4 v[ADD_VPT];
    #pragma unroll
    for (int k = 0; k < ADD_VPT; k++)
        v[k] = __ldcs(x4 + base + (size_t)k * ADD_TPB);

    // Wait for the FULL pool+MLP grid (k1 never triggers early, so this is
    // completion of k1) before touching g_term.
    cudaGridDependencySynchronize();

    #pragma unroll
    for (int k = 0; k < ADD_VPT; k++) {
        const size_t i = base + (size_t)k * ADD_TPB;
        const int c4 = (int)(i & (C4 - 1));
        const int b  = (int)(i >> 18);                 // HW*C/4 = 2^18 per batch
        const float4 t = reinterpret_cast<const float4*>(g_term)[b * C4 + c4];
        v[k].x += t.x; v[k].y += t.y; v[k].z += t.z; v[k].w += t.w;
        __stcs(out4 + i, v[k]);
    }
}

extern "C" void kernel_launch(void* const* d_in, const int* in_sizes, int n_in,
                              void* d_out, int out_size)
{
    const float* x     = (const float*)d_in[0];
    const float* wm    = (const float*)d_in[1];
    const float* bm    = (const float*)d_in[2];
    const float* w1    = (const float*)d_in[3];
    const float* b1    = (const float*)d_in[4];
    const float* gamma = (const float*)d_in[5];
    const float* beta  = (const float*)d_in[6];
    const float* w2    = (const float*)d_in[7];
    const float* b2    = (const float*)d_in[8];
    float* out = (float*)d_out;

    const int B = in_sizes[0] / (HW * C);

    gc_pool_mlp_kernel<<<B * NCHUNK, 256>>>(x, wm, bm, w1, b1, gamma, beta, w2, b2);

    // Secondary kernel with programmatic dependent launch: its blocks may
    // start (and issue x prefetch loads) while k1 drains.
    const int n4 = out_size / 4;                 // 8,388,608 = 4096 * 2048
    const int elems_per_blk = ADD_TPB * ADD_VPT; // 2048

    cudaLaunchConfig_t cfg = {};
    cfg.gridDim  = dim3(n4 / elems_per_blk, 1, 1);
    cfg.blockDim = dim3(ADD_TPB, 1, 1);
    cfg.dynamicSmemBytes = 0;
    cfg.stream = 0;
    cudaLaunchAttribute attrs[1];
    attrs[0].id = cudaLaunchAttributeProgrammaticStreamSerialization;
    attrs[0].val.programmaticStreamSerializationAllowed = 1;
    cfg.attrs = attrs;
    cfg.numAttrs = 1;
    cudaLaunchKernelEx(&cfg, gc_add_kernel, (const float4*)x, (float4*)out);
}